// round 10
// baseline (speedup 1.0000x reference)
#include <cuda_runtime.h>
#include <cuda_bf16.h>
#include <cstdint>

// ===========================================================================
// RouteNTMMatrix: e4m3 mma.sync.m16n8k32 + ldmatrix (byte-pair b16 view);
// two independent 256-thread pipelines per CTA; 64-row tiles; 1 barrier/tile.
//   x = (64 r)·(128 t) = 8192·r·t in e4m3;  gcp = relu(acc)·(fc_w/8192)
// ===========================================================================

#define DIM    256
#define KOUT   100
#define CDIM   5
#define XQ     68             // row stride in words (256B data + 16B pad); 68%32=4 -> conflict-free

// word offsets in dynamic smem
#define WP_W   0                            // w e4m3 [128n][68]
#define XB_W   (WP_W + 128 * XQ)            // x e4m3: 2 groups x 2 slots x [64][68]
#define FCS_W  (XB_W + 4 * 64 * XQ)
#define FCI_W  (FCS_W + 128)
#define BIA_W  (FCI_W + 32)
#define OAC_W  (BIA_W + 32)                 // partials: 2 groups x 2 slots x 64
#define RV5_W  (OAC_W + 256)                // ra prefetch: 2 groups x 3 slots x 64 x 5
#define TV5_W  (RV5_W + 2 * 3 * 64 * CDIM)
#define SM_WORDS (TV5_W + 2 * 3 * 64 * CDIM)   // 30400 words = 121600 B

#define RSCALE 64.0f
#define TSCALE 128.0f
#define INVSCALE (1.0f / 8192.0f)

__device__ float g_ra[100000 * CDIM];
__device__ float g_tb[2048   * CDIM];
__device__ __nv_bfloat16 g_rtb[100000 * DIM];   // bf16(64*r)
__device__ __nv_bfloat16 g_ttb[2048   * DIM];   // bf16(128*t)

__device__ __forceinline__ uint32_t pack_bf16(float lo, float hi) {
    uint32_t u;
    asm("cvt.rn.bf16x2.f32 %0, %1, %2;" : "=r"(u) : "f"(hi), "f"(lo));
    return u;
}
__device__ __forceinline__ uint32_t pack_e4m3x4(float f0, float f1, float f2, float f3) {
    uint32_t u;
    asm("{ .reg .b16 l, h;\n\t"
        "cvt.rn.satfinite.e4m3x2.f32 l, %2, %1;\n\t"
        "cvt.rn.satfinite.e4m3x2.f32 h, %4, %3;\n\t"
        "mov.b32 %0, {l, h}; }"
        : "=r"(u) : "f"(f0), "f"(f1), "f"(f2), "f"(f3));
    return u;
}
__device__ __forceinline__ void mma_fp8(float* d, const uint32_t* a,
                                        uint32_t b0, uint32_t b1) {
    asm volatile("mma.sync.aligned.m16n8k32.row.col.f32.e4m3.e4m3.f32 "
                 "{%0,%1,%2,%3}, {%4,%5,%6,%7}, {%8,%9}, {%0,%1,%2,%3};"
                 : "+f"(d[0]), "+f"(d[1]), "+f"(d[2]), "+f"(d[3])
                 : "r"(a[0]), "r"(a[1]), "r"(a[2]), "r"(a[3]), "r"(b0), "r"(b1));
}
#define LDSM_X4(r0, r1, r2, r3, addr) \
    asm volatile("ldmatrix.sync.aligned.m8n8.x4.shared.b16 {%0,%1,%2,%3}, [%4];" \
                 : "=r"(r0), "=r"(r1), "=r"(r2), "=r"(r3) : "r"(addr))
#define BARG(id) asm volatile("bar.sync %0, %1;" :: "r"(id), "r"(256) : "memory")

__device__ __forceinline__ uint32_t smem_u32(const void* p) {
    uint32_t a;
    asm("{ .reg .u64 t; cvta.to.shared.u64 t, %1; cvt.u32.u64 %0, t; }" : "=r"(a) : "l"(p));
    return a;
}
// 8 bf16 x 8 bf16 -> 8 e4m3 bytes of the product
__device__ __forceinline__ uint2 mul_cvt8(uint4 a, uint4 b) {
    const __nv_bfloat162* pa = reinterpret_cast<const __nv_bfloat162*>(&a);
    const __nv_bfloat162* pb = reinterpret_cast<const __nv_bfloat162*>(&b);
    const float2 f0 = __bfloat1622float2(__hmul2(pa[0], pb[0]));
    const float2 f1 = __bfloat1622float2(__hmul2(pa[1], pb[1]));
    const float2 f2 = __bfloat1622float2(__hmul2(pa[2], pb[2]));
    const float2 f3 = __bfloat1622float2(__hmul2(pa[3], pb[3]));
    uint2 r;
    r.x = pack_e4m3x4(f0.x, f0.y, f1.x, f1.y);
    r.y = pack_e4m3x4(f2.x, f2.y, f3.x, f3.y);
    return r;
}

// ---------------------------------------------------------------------------
// proj + convert: warp per 4 rows (8 LDG.128 in flight). Single read feeds
// projection (unscaled fp32) and scaled-bf16 conversion.
// ---------------------------------------------------------------------------
__global__ __launch_bounds__(512)
void proj_conv(const float* __restrict__ route_table,
               const float* __restrict__ time_table,
               const float* __restrict__ mode_a,
               const float* __restrict__ mode_b,
               float* __restrict__ ra_tab, float* __restrict__ tb_tab,
               __nv_bfloat16* __restrict__ rtb, __nv_bfloat16* __restrict__ ttb,
               int n_routes, int n_time)
{
    __shared__ float PtA[CDIM * 2 * 4 * 32];
    __shared__ float PtB[CDIM * 2 * 4 * 32];
    const int tid = threadIdx.x;
    for (int i = tid; i < CDIM * 2 * 4 * 32; i += 512) {
        const int ln = i & 31, j = (i >> 5) & 3, h = (i >> 7) & 1, c = i >> 8;
        const int d = h * 128 + 4 * ln + j;
        PtA[i] = __ldg(mode_a + d * CDIM + c);
        PtB[i] = __ldg(mode_b + d * CDIM + c);
    }
    __syncthreads();

    const int lane  = tid & 31;
    const int total = n_routes + n_time;
    const int base  = (blockIdx.x * 16 + (tid >> 5)) * 4;
    if (base >= total) return;

    // batched loads for 4 rows
    float4 va[4][2];
    int   rws[4];
    bool  isr[4];
#pragma unroll
    for (int jr = 0; jr < 4; jr++) {
        const int row = min(base + jr, total - 1);
        rws[jr] = row;
        isr[jr] = row < n_routes;
        const float* rf = (isr[jr] ? route_table : time_table)
                          + (size_t)(isr[jr] ? row : row - n_routes) * DIM;
        const float4* p = reinterpret_cast<const float4*>(rf);
        va[jr][0] = __ldg(p + lane);
        va[jr][1] = __ldg(p + 32 + lane);
    }

#pragma unroll
    for (int jr = 0; jr < 4; jr++) {
        if (jr > 0 && base + jr >= total) break;
        const bool is_r = isr[jr];
        const int  lrow = is_r ? rws[jr] : rws[jr] - n_routes;
        const float4 v0 = va[jr][0], v1 = va[jr][1];
        const float* Pt = is_r ? PtA : PtB;
        const float  sc = is_r ? RSCALE : TSCALE;

        uint2* brow = reinterpret_cast<uint2*>((is_r ? rtb : ttb) + (size_t)lrow * DIM);
        brow[lane]      = make_uint2(pack_bf16(sc * v0.x, sc * v0.y), pack_bf16(sc * v0.z, sc * v0.w));
        brow[lane + 32] = make_uint2(pack_bf16(sc * v1.x, sc * v1.y), pack_bf16(sc * v1.z, sc * v1.w));

        const float vv[2][4] = {{v0.x, v0.y, v0.z, v0.w}, {v1.x, v1.y, v1.z, v1.w}};
        float acc[CDIM] = {0.f, 0.f, 0.f, 0.f, 0.f};
#pragma unroll
        for (int c = 0; c < CDIM; c++)
#pragma unroll
            for (int h = 0; h < 2; h++)
#pragma unroll
                for (int j = 0; j < 4; j++)
                    acc[c] = fmaf(vv[h][j], Pt[((c * 2 + h) * 4 + j) * 32 + lane], acc[c]);

#pragma unroll
        for (int off = 16; off; off >>= 1)
#pragma unroll
            for (int c = 0; c < CDIM; c++) acc[c] += __shfl_xor_sync(0xffffffffu, acc[c], off);

        if (lane == 0) {
            float* o = (is_r ? ra_tab : tb_tab) + (size_t)lrow * CDIM;
#pragma unroll
            for (int c = 0; c < CDIM; c++) o[c] = acc[c];
        }
    }
}

// ---------------------------------------------------------------------------
// Main persistent kernel: 512 threads = 2 independent 256-thread groups.
// ---------------------------------------------------------------------------
__global__ __launch_bounds__(512, 1)
void main_kernel(const int*   __restrict__ route_idx,
                 const int*   __restrict__ time_idx,
                 const uint4* __restrict__ RTB,
                 const uint4* __restrict__ TTB,
                 const float* __restrict__ w,
                 const float* __restrict__ fc_w,
                 const float* __restrict__ fc_b,
                 const float* __restrict__ mode_bias,
                 const float* __restrict__ ra_tab,
                 const float* __restrict__ tb_tab,
                 float*       __restrict__ out,
                 int batch, int ntiles)
{
    extern __shared__ uint32_t smu[];
    uint32_t* wq  = smu + WP_W;
    float*    fcs = reinterpret_cast<float*>(smu + FCS_W);
    float*    fci = reinterpret_cast<float*>(smu + FCI_W);
    float*    bia = reinterpret_cast<float*>(smu + BIA_W);

    const int tid  = threadIdx.x;
    const int gid  = tid >> 8;
    const int lt   = tid & 255;
    const int lw   = lt >> 5;
    const int lane = tid & 31;
    const uint32_t sm_u32 = smem_u32(smu);

    // stage w as e4m3: wq[n*XQ + kw] = bytes {w[4kw..4kw+3][n]}
    for (int i = tid; i < 64 * 128; i += 512) {
        const int kw = i >> 7, n = i & 127;
        float f[4];
#pragma unroll
        for (int j = 0; j < 4; j++)
            f[j] = (n < KOUT) ? __ldg(w + (4 * kw + j) * KOUT + n) : 0.f;
        wq[n * XQ + kw] = pack_e4m3x4(f[0], f[1], f[2], f[3]);
    }
    if (tid < 128)                 fcs[tid] = ((tid < KOUT) ? __ldg(fc_w + tid) : 0.f) * INVSCALE;
    if (tid >= 128 && tid < 153)   fci[tid - 128] = __ldg(fc_w + KOUT + tid - 128);
    if (tid >= 160 && tid < 185)   bia[tid - 160] = __ldg(mode_bias + tid - 160);
    if (tid < 256)                 reinterpret_cast<float*>(smu + OAC_W)[tid] = 0.f;

    const float fcb = __ldg(fc_b);

    float*    oacg = reinterpret_cast<float*>(smu + OAC_W) + gid * 128;
    uint32_t* xg   = smu + XB_W + gid * (2 * 64 * XQ);
    float*    rv5g = reinterpret_cast<float*>(smu + RV5_W) + gid * (3 * 64 * CDIM);
    float*    tv5g = reinterpret_cast<float*>(smu + TV5_W) + gid * (3 * 64 * CDIM);

    const int mq = lw >> 2, nq = lw & 3;
    const int t  = lane & 3;
    const int barid = 1 + gid;

    // ldmatrix addressing (b16 view of fp8 rows; 16B half-steps)
    const int a_row = (lane & 7) + ((lane >> 3) & 1) * 8;
    const int a_kq  = (lane >> 4) * 4;                     // words (16B)
    const int b_n   = ((lane >> 4) << 3) + (lane & 7);
    const int b_kq  = ((lane >> 3) & 1) * 4;
    uint32_t bAddr[2];
#pragma unroll
    for (int p = 0; p < 2; p++)
        bAddr[p] = sm_u32 + (WP_W + (nq * 32 + p * 16 + b_n) * XQ + b_kq) * 4;

    const int step  = gridDim.x * 2;
    const int first = blockIdx.x * 2 + gid;
    const int li    = lane & 7;

    __syncthreads();   // staging visible to both groups

    // ---- prologue: gather first tile -> x slot 0, rv5 slot 0 ----
    {
        const int ei = min(first * 64 + lw * 8 + li, batch - 1);
        const int ridx = __ldg(route_idx + ei);
        const int tidx = __ldg(time_idx  + ei);
        if (lane < 8) {
#pragma unroll
            for (int c = 0; c < CDIM; c++) {
                rv5g[(lw * 8 + li) * CDIM + c] = __ldg(ra_tab + (size_t)ridx * CDIM + c);
                tv5g[(lw * 8 + li) * CDIM + c] = __ldg(tb_tab + (size_t)tidx * CDIM + c);
            }
        }
#pragma unroll
        for (int h = 0; h < 2; h++) {
            uint4 rr[4], tt[4];
#pragma unroll
            for (int i = 0; i < 4; i++) {
                const int r0 = __shfl_sync(0xffffffffu, ridx, h * 4 + i);
                const int t0 = __shfl_sync(0xffffffffu, tidx, h * 4 + i);
                rr[i] = __ldg(RTB + (size_t)r0 * 32 + lane);
                tt[i] = __ldg(TTB + (size_t)t0 * 32 + lane);
            }
#pragma unroll
            for (int i = 0; i < 4; i++)
                *reinterpret_cast<uint2*>(reinterpret_cast<char*>(xg)
                    + (lw * 8 + h * 4 + i) * (XQ * 4) + lane * 8) = mul_cvt8(rr[i], tt[i]);
        }
    }
    BARG(barid);

    int it = 0;
    for (int tile = first; tile < ntiles; tile += step, it++) {
        const int s   = it & 1;
        const int rs  = it % 3;            // rv5 slot for current tile
        const int rsn = (it + 1) % 3;      // rv5 slot for next tile
        uint32_t* xb_cur = xg + s * (64 * XQ);
        char*     xb_nxt = reinterpret_cast<char*>(xg + (s ^ 1) * (64 * XQ));
        const bool have_next = (tile + step < ntiles);

        int nridx = 0, ntidx = 0;
        uint4 rr[4], tt[4];

        // ---- issue next-tile idx + rows 0-3 ----
        if (have_next) {
            const int ei = min((tile + step) * 64 + lw * 8 + li, batch - 1);
            nridx = __ldg(route_idx + ei);
            ntidx = __ldg(time_idx  + ei);
#pragma unroll
            for (int i = 0; i < 4; i++) {
                const int r0 = __shfl_sync(0xffffffffu, nridx, i);
                const int t0 = __shfl_sync(0xffffffffu, ntidx, i);
                rr[i] = __ldg(RTB + (size_t)r0 * 32 + lane);
                tt[i] = __ldg(TTB + (size_t)t0 * 32 + lane);
            }
            if (lane < 8) {
#pragma unroll
                for (int c = 0; c < CDIM; c++) {
                    rv5g[(rsn * 64 + lw * 8 + li) * CDIM + c] = __ldg(ra_tab + (size_t)nridx * CDIM + c);
                    tv5g[(rsn * 64 + lw * 8 + li) * CDIM + c] = __ldg(tb_tab + (size_t)ntidx * CDIM + c);
                }
            }
        }

        float acc[2][4][4];
#pragma unroll
        for (int m = 0; m < 2; m++)
#pragma unroll
            for (int n = 0; n < 4; n++)
#pragma unroll
                for (int q = 0; q < 4; q++) acc[m][n][q] = 0.f;

        uint32_t aAddr[2];
#pragma unroll
        for (int m = 0; m < 2; m++)
            aAddr[m] = sm_u32 + (uint32_t)((xb_cur - smu)
                       + (mq * 32 + m * 16 + a_row) * XQ + a_kq) * 4;

        // ---- MMA kc 0-3 (K 0..127) — hides next-tile LDG latency ----
#pragma unroll
        for (int kc = 0; kc < 4; kc++) {
            const uint32_t kb = kc * 32;
            uint32_t bb[8];
            LDSM_X4(bb[0], bb[1], bb[2], bb[3], bAddr[0] + kb);
            LDSM_X4(bb[4], bb[5], bb[6], bb[7], bAddr[1] + kb);
#pragma unroll
            for (int m = 0; m < 2; m++) {
                uint32_t a[4];
                LDSM_X4(a[0], a[1], a[2], a[3], aAddr[m] + kb);
                mma_fp8(acc[m][0], a, bb[0], bb[1]);
                mma_fp8(acc[m][1], a, bb[2], bb[3]);
                mma_fp8(acc[m][2], a, bb[4], bb[5]);
                mma_fp8(acc[m][3], a, bb[6], bb[7]);
            }
        }

        // ---- commit rows 0-3; issue rows 4-7 ----
        if (have_next) {
#pragma unroll
            for (int i = 0; i < 4; i++)
                *reinterpret_cast<uint2*>(xb_nxt + (lw * 8 + i) * (XQ * 4) + lane * 8)
                    = mul_cvt8(rr[i], tt[i]);
#pragma unroll
            for (int i = 0; i < 4; i++) {
                const int r0 = __shfl_sync(0xffffffffu, nridx, 4 + i);
                const int t0 = __shfl_sync(0xffffffffu, ntidx, 4 + i);
                rr[i] = __ldg(RTB + (size_t)r0 * 32 + lane);
                tt[i] = __ldg(TTB + (size_t)t0 * 32 + lane);
            }
        }

        // ---- MMA kc 4-7 (K 128..255) ----
#pragma unroll
        for (int kc = 4; kc < 8; kc++) {
            const uint32_t kb = kc * 32;
            uint32_t bb[8];
            LDSM_X4(bb[0], bb[1], bb[2], bb[3], bAddr[0] + kb);
            LDSM_X4(bb[4], bb[5], bb[6], bb[7], bAddr[1] + kb);
#pragma unroll
            for (int m = 0; m < 2; m++) {
                uint32_t a[4];
                LDSM_X4(a[0], a[1], a[2], a[3], aAddr[m] + kb);
                mma_fp8(acc[m][0], a, bb[0], bb[1]);
                mma_fp8(acc[m][1], a, bb[2], bb[3]);
                mma_fp8(acc[m][2], a, bb[4], bb[5]);
                mma_fp8(acc[m][3], a, bb[6], bb[7]);
            }
        }

        // ---- commit rows 4-7 ----
        if (have_next) {
#pragma unroll
            for (int i = 0; i < 4; i++)
                *reinterpret_cast<uint2*>(xb_nxt + (lw * 8 + 4 + i) * (XQ * 4) + lane * 8)
                    = mul_cvt8(rr[i], tt[i]);
        }

        // ---- fold relu * (fc_w/8192) -> per-row partials (slot s) ----
        float* oacs = oacg + s * 64;
#pragma unroll
        for (int m = 0; m < 2; m++) {
            float p0 = 0.f, p1 = 0.f;
#pragma unroll
            for (int n = 0; n < 4; n++) {
                const int col = nq * 32 + n * 8 + 2 * t;
                const float f0 = fcs[col], f1 = fcs[col + 1];
                p0 = fmaf(f0, fmaxf(acc[m][n][0], 0.f), p0);
                p0 = fmaf(f1, fmaxf(acc[m][n][1], 0.f), p0);
                p1 = fmaf(f0, fmaxf(acc[m][n][2], 0.f), p1);
                p1 = fmaf(f1, fmaxf(acc[m][n][3], 0.f), p1);
            }
            p0 += __shfl_xor_sync(0xffffffffu, p0, 1);
            p0 += __shfl_xor_sync(0xffffffffu, p0, 2);
            p1 += __shfl_xor_sync(0xffffffffu, p1, 1);
            p1 += __shfl_xor_sync(0xffffffffu, p1, 2);
            if (t == 0) {
                const int row = mq * 32 + m * 16 + (lane >> 2);
                atomicAdd(oacs + row, p0);
                atomicAdd(oacs + row + 8, p1);
            }
        }
        BARG(barid);   // partials + slot^1 x-stores complete

        // ---- epilogue: 4 threads/row; reads rv5 slot rs, oac slot s ----
        {
            const int row = lt >> 2;
            const int p   = lt & 3;
            const int eo  = tile * 64 + row;
            const float* rv = rv5g + (rs * 64 + row) * CDIM;
            const float* tv = tv5g + (rs * 64 + row) * CDIM;
            const int start = p ? (1 + p * 6) : 0;
            const int cnt   = p ? 6 : 7;
            float val = 0.f;
#pragma unroll
            for (int k = 0; k < 7; k++) {
                if (k < cnt) {
                    const int idx = start + k;
                    const int i5  = idx / 5, j5 = idx - 5 * i5;
                    const float x  = fmaf(rv[i5], tv[j5], bia[idx]);
                    const float sg = 1.0f / (1.0f + __expf(-x));
                    val = fmaf(fci[idx], sg, val);
                }
            }
            val += __shfl_xor_sync(0xffffffffu, val, 1);
            val += __shfl_xor_sync(0xffffffffu, val, 2);
            if (p == 0) {
                if (eo < batch) out[eo] = fcb + oacs[row] + val;
                oacs[row] = 0.f;
            }
        }
        // no second barrier: next tile uses oac slot s^1, rv5 slot rsn;
        // slot-s reuse is fenced by the NEXT iteration's BARG.
    }
}

// ---------------------------------------------------------------------------
extern "C" void kernel_launch(void* const* d_in, const int* in_sizes, int n_in,
                              void* d_out, int out_size)
{
    const int*   route_idx   = (const int*)  d_in[0];
    const int*   time_idx    = (const int*)  d_in[1];
    const float* route_table = (const float*)d_in[2];
    const float* time_table  = (const float*)d_in[3];
    const float* w           = (const float*)d_in[4];
    const float* mode_a      = (const float*)d_in[5];
    const float* mode_b      = (const float*)d_in[6];
    const float* mode_bias   = (const float*)d_in[7];
    const float* fc_w        = (const float*)d_in[8];
    const float* fc_b        = (const float*)d_in[9];
    float*       out         = (float*)d_out;

    const int batch    = in_sizes[0];
    const int n_routes = in_sizes[2] / DIM;
    const int n_time   = in_sizes[3] / DIM;

    float *ra_ptr = nullptr, *tb_ptr = nullptr;
    __nv_bfloat16 *rtb_ptr = nullptr, *ttb_ptr = nullptr;
    cudaGetSymbolAddress((void**)&ra_ptr,  g_ra);
    cudaGetSymbolAddress((void**)&tb_ptr,  g_tb);
    cudaGetSymbolAddress((void**)&rtb_ptr, g_rtb);
    cudaGetSymbolAddress((void**)&ttb_ptr, g_ttb);

    {
        const int total = n_routes + n_time;
        proj_conv<<<(total + 63) / 64, 512>>>(route_table, time_table, mode_a, mode_b,
                                              ra_ptr, tb_ptr, rtb_ptr, ttb_ptr,
                                              n_routes, n_time);
    }

    const int ntiles = (batch + 63) / 64;
    const int smem_bytes = SM_WORDS * 4;   // 121600
    cudaFuncSetAttribute(main_kernel, cudaFuncAttributeMaxDynamicSharedMemorySize, smem_bytes);

    int grid = 148;
    main_kernel<<<grid, 512, smem_bytes>>>(route_idx, time_idx,
                                           (const uint4*)rtb_ptr, (const uint4*)ttb_ptr,
                                           w, fc_w, fc_b, mode_bias,
                                           ra_ptr, tb_ptr, out, batch, ntiles);
}

// round 11
// speedup vs baseline: 1.0258x; 1.0258x over previous
#include <cuda_runtime.h>
#include <cuda_fp16.h>
#include <cstdint>

// ===========================================================================
// RouteNTMMatrix: e4m3 mma.sync.m16n8k32 + ldmatrix (b16 view), f16 scaled
// tables with single-cvt fp8 packing; two independent 256-thread pipelines.
//   x = (64 r)·(128 t) = 8192·r·t in e4m3;  gcp = relu(acc)·(fc_w/8192)
// ===========================================================================

#define DIM    256
#define KOUT   100
#define CDIM   5
#define XQ     68             // row stride in words (256B data + 16B pad); 68%32=4 -> conflict-free

// word offsets in dynamic smem
#define WP_W   0                            // w e4m3 [128n][68]
#define XB_W   (WP_W + 128 * XQ)            // x e4m3: 2 groups x 2 slots x [64][68]
#define FCS_W  (XB_W + 4 * 64 * XQ)
#define FCI_W  (FCS_W + 128)
#define BIA_W  (FCI_W + 32)
#define OAC_W  (BIA_W + 32)                 // partials: 2 groups x 2 slots x 64
#define RV5_W  (OAC_W + 256)                // ra prefetch: 2 groups x 3 slots x 64 x 5
#define TV5_W  (RV5_W + 2 * 3 * 64 * CDIM)
#define SM_WORDS (TV5_W + 2 * 3 * 64 * CDIM)   // 30400 words = 121600 B

#define RSCALE 64.0f
#define TSCALE 128.0f
#define INVSCALE (1.0f / 8192.0f)

__device__ float g_ra[100000 * CDIM];
__device__ float g_tb[2048   * CDIM];
__device__ __half g_rtb[100000 * DIM];   // f16(64*r)
__device__ __half g_ttb[2048   * DIM];   // f16(128*t)

__device__ __forceinline__ uint32_t pack_e4m3x4(float f0, float f1, float f2, float f3) {
    uint32_t u;
    asm("{ .reg .b16 l, h;\n\t"
        "cvt.rn.satfinite.e4m3x2.f32 l, %2, %1;\n\t"
        "cvt.rn.satfinite.e4m3x2.f32 h, %4, %3;\n\t"
        "mov.b32 %0, {l, h}; }"
        : "=r"(u) : "f"(f0), "f"(f1), "f"(f2), "f"(f3));
    return u;
}
__device__ __forceinline__ void mma_fp8(float* d, const uint32_t* a,
                                        uint32_t b0, uint32_t b1) {
    asm volatile("mma.sync.aligned.m16n8k32.row.col.f32.e4m3.e4m3.f32 "
                 "{%0,%1,%2,%3}, {%4,%5,%6,%7}, {%8,%9}, {%0,%1,%2,%3};"
                 : "+f"(d[0]), "+f"(d[1]), "+f"(d[2]), "+f"(d[3])
                 : "r"(a[0]), "r"(a[1]), "r"(a[2]), "r"(a[3]), "r"(b0), "r"(b1));
}
#define LDSM_X4(r0, r1, r2, r3, addr) \
    asm volatile("ldmatrix.sync.aligned.m8n8.x4.shared.b16 {%0,%1,%2,%3}, [%4];" \
                 : "=r"(r0), "=r"(r1), "=r"(r2), "=r"(r3) : "r"(addr))
#define BARG(id) asm volatile("bar.sync %0, %1;" :: "r"(id), "r"(256) : "memory")

__device__ __forceinline__ uint32_t smem_u32(const void* p) {
    uint32_t a;
    asm("{ .reg .u64 t; cvta.to.shared.u64 t, %1; cvt.u32.u64 %0, t; }" : "=r"(a) : "l"(p));
    return a;
}
// 8 f16 x 8 f16 -> 8 e4m3 bytes of the product (lean: 4 hmul2 + 4 cvt + 2 mov)
__device__ __forceinline__ uint2 mul_cvt8(uint4 a, uint4 b) {
    const __half2* pa = reinterpret_cast<const __half2*>(&a);
    const __half2* pb = reinterpret_cast<const __half2*>(&b);
    __half2 h0 = __hmul2(pa[0], pb[0]);
    __half2 h1 = __hmul2(pa[1], pb[1]);
    __half2 h2 = __hmul2(pa[2], pb[2]);
    __half2 h3 = __hmul2(pa[3], pb[3]);
    uint2 r;
    asm("{ .reg .b16 x0, x1, x2, x3;\n\t"
        "cvt.rn.satfinite.e4m3x2.f16x2 x0, %2;\n\t"
        "cvt.rn.satfinite.e4m3x2.f16x2 x1, %3;\n\t"
        "cvt.rn.satfinite.e4m3x2.f16x2 x2, %4;\n\t"
        "cvt.rn.satfinite.e4m3x2.f16x2 x3, %5;\n\t"
        "mov.b32 %0, {x0, x1};\n\t"
        "mov.b32 %1, {x2, x3}; }"
        : "=r"(r.x), "=r"(r.y)
        : "r"(*reinterpret_cast<uint32_t*>(&h0)),
          "r"(*reinterpret_cast<uint32_t*>(&h1)),
          "r"(*reinterpret_cast<uint32_t*>(&h2)),
          "r"(*reinterpret_cast<uint32_t*>(&h3)));
    return r;
}

// ---------------------------------------------------------------------------
// proj + convert: warp per 4 rows (8 LDG.128 in flight). Single read feeds
// projection (unscaled fp32) and scaled-f16 conversion.
// ---------------------------------------------------------------------------
__global__ __launch_bounds__(512)
void proj_conv(const float* __restrict__ route_table,
               const float* __restrict__ time_table,
               const float* __restrict__ mode_a,
               const float* __restrict__ mode_b,
               float* __restrict__ ra_tab, float* __restrict__ tb_tab,
               __half* __restrict__ rtb, __half* __restrict__ ttb,
               int n_routes, int n_time)
{
    __shared__ float PtA[CDIM * 2 * 4 * 32];
    __shared__ float PtB[CDIM * 2 * 4 * 32];
    const int tid = threadIdx.x;
    for (int i = tid; i < CDIM * 2 * 4 * 32; i += 512) {
        const int ln = i & 31, j = (i >> 5) & 3, h = (i >> 7) & 1, c = i >> 8;
        const int d = h * 128 + 4 * ln + j;
        PtA[i] = __ldg(mode_a + d * CDIM + c);
        PtB[i] = __ldg(mode_b + d * CDIM + c);
    }
    __syncthreads();

    const int lane  = tid & 31;
    const int total = n_routes + n_time;
    const int base  = (blockIdx.x * 16 + (tid >> 5)) * 4;
    if (base >= total) return;

    float4 va[4][2];
    int   rws[4];
    bool  isr[4];
#pragma unroll
    for (int jr = 0; jr < 4; jr++) {
        const int row = min(base + jr, total - 1);
        rws[jr] = row;
        isr[jr] = row < n_routes;
        const float* rf = (isr[jr] ? route_table : time_table)
                          + (size_t)(isr[jr] ? row : row - n_routes) * DIM;
        const float4* p = reinterpret_cast<const float4*>(rf);
        va[jr][0] = __ldg(p + lane);
        va[jr][1] = __ldg(p + 32 + lane);
    }

#pragma unroll
    for (int jr = 0; jr < 4; jr++) {
        if (jr > 0 && base + jr >= total) break;
        const bool is_r = isr[jr];
        const int  lrow = is_r ? rws[jr] : rws[jr] - n_routes;
        const float4 v0 = va[jr][0], v1 = va[jr][1];
        const float* Pt = is_r ? PtA : PtB;
        const float  sc = is_r ? RSCALE : TSCALE;

        __half2* brow = reinterpret_cast<__half2*>((is_r ? rtb : ttb) + (size_t)lrow * DIM);
        __half2 c0 = __floats2half2_rn(sc * v0.x, sc * v0.y);
        __half2 c1 = __floats2half2_rn(sc * v0.z, sc * v0.w);
        __half2 c2 = __floats2half2_rn(sc * v1.x, sc * v1.y);
        __half2 c3 = __floats2half2_rn(sc * v1.z, sc * v1.w);
        *reinterpret_cast<uint2*>(brow + 2 * lane) =
            make_uint2(*reinterpret_cast<uint32_t*>(&c0), *reinterpret_cast<uint32_t*>(&c1));
        *reinterpret_cast<uint2*>(brow + 64 + 2 * lane) =
            make_uint2(*reinterpret_cast<uint32_t*>(&c2), *reinterpret_cast<uint32_t*>(&c3));

        const float vv[2][4] = {{v0.x, v0.y, v0.z, v0.w}, {v1.x, v1.y, v1.z, v1.w}};
        float acc[CDIM] = {0.f, 0.f, 0.f, 0.f, 0.f};
#pragma unroll
        for (int c = 0; c < CDIM; c++)
#pragma unroll
            for (int h = 0; h < 2; h++)
#pragma unroll
                for (int j = 0; j < 4; j++)
                    acc[c] = fmaf(vv[h][j], Pt[((c * 2 + h) * 4 + j) * 32 + lane], acc[c]);

#pragma unroll
        for (int off = 16; off; off >>= 1)
#pragma unroll
            for (int c = 0; c < CDIM; c++) acc[c] += __shfl_xor_sync(0xffffffffu, acc[c], off);

        if (lane == 0) {
            float* o = (is_r ? ra_tab : tb_tab) + (size_t)lrow * CDIM;
#pragma unroll
            for (int c = 0; c < CDIM; c++) o[c] = acc[c];
        }
    }
}

// ---------------------------------------------------------------------------
// Main persistent kernel: 512 threads = 2 independent 256-thread groups.
// ---------------------------------------------------------------------------
__global__ __launch_bounds__(512, 1)
void main_kernel(const int*   __restrict__ route_idx,
                 const int*   __restrict__ time_idx,
                 const uint4* __restrict__ RTB,
                 const uint4* __restrict__ TTB,
                 const float* __restrict__ w,
                 const float* __restrict__ fc_w,
                 const float* __restrict__ fc_b,
                 const float* __restrict__ mode_bias,
                 const float* __restrict__ ra_tab,
                 const float* __restrict__ tb_tab,
                 float*       __restrict__ out,
                 int batch, int ntiles)
{
    extern __shared__ uint32_t smu[];
    uint32_t* wq  = smu + WP_W;
    float*    fcs = reinterpret_cast<float*>(smu + FCS_W);
    float*    fci = reinterpret_cast<float*>(smu + FCI_W);
    float*    bia = reinterpret_cast<float*>(smu + BIA_W);

    const int tid  = threadIdx.x;
    const int gid  = tid >> 8;
    const int lt   = tid & 255;
    const int lw   = lt >> 5;
    const int lane = tid & 31;
    const uint32_t sm_u32 = smem_u32(smu);

    // stage w as e4m3: wq[n*XQ + kw] = bytes {w[4kw..4kw+3][n]}
    for (int i = tid; i < 64 * 128; i += 512) {
        const int kw = i >> 7, n = i & 127;
        float f[4];
#pragma unroll
        for (int j = 0; j < 4; j++)
            f[j] = (n < KOUT) ? __ldg(w + (4 * kw + j) * KOUT + n) : 0.f;
        wq[n * XQ + kw] = pack_e4m3x4(f[0], f[1], f[2], f[3]);
    }
    if (tid < 128)                 fcs[tid] = ((tid < KOUT) ? __ldg(fc_w + tid) : 0.f) * INVSCALE;
    if (tid >= 128 && tid < 153)   fci[tid - 128] = __ldg(fc_w + KOUT + tid - 128);
    if (tid >= 160 && tid < 185)   bia[tid - 160] = __ldg(mode_bias + tid - 160);
    if (tid < 256)                 reinterpret_cast<float*>(smu + OAC_W)[tid] = 0.f;

    const float fcb = __ldg(fc_b);

    float*    oacg = reinterpret_cast<float*>(smu + OAC_W) + gid * 128;
    uint32_t* xg   = smu + XB_W + gid * (2 * 64 * XQ);
    float*    rv5g = reinterpret_cast<float*>(smu + RV5_W) + gid * (3 * 64 * CDIM);
    float*    tv5g = reinterpret_cast<float*>(smu + TV5_W) + gid * (3 * 64 * CDIM);

    const int mq = lw >> 2, nq = lw & 3;
    const int t  = lane & 3;
    const int barid = 1 + gid;

    // ldmatrix addressing (b16 view of fp8 rows)
    const int a_row = (lane & 7) + ((lane >> 3) & 1) * 8;
    const int a_kq  = (lane >> 4) * 4;
    const int b_n   = ((lane >> 4) << 3) + (lane & 7);
    const int b_kq  = ((lane >> 3) & 1) * 4;
    uint32_t bAddr[2];
#pragma unroll
    for (int p = 0; p < 2; p++)
        bAddr[p] = sm_u32 + (WP_W + (nq * 32 + p * 16 + b_n) * XQ + b_kq) * 4;

    const int step  = gridDim.x * 2;
    const int first = blockIdx.x * 2 + gid;
    const int li    = lane & 7;

    __syncthreads();

    // ---- prologue: gather first tile -> x slot 0, rv5 slot 0 ----
    {
        const int ei = min(first * 64 + lw * 8 + li, batch - 1);
        const int ridx = __ldg(route_idx + ei);
        const int tidx = __ldg(time_idx  + ei);
        if (lane < 8) {
#pragma unroll
            for (int c = 0; c < CDIM; c++) {
                rv5g[(lw * 8 + li) * CDIM + c] = __ldg(ra_tab + (size_t)ridx * CDIM + c);
                tv5g[(lw * 8 + li) * CDIM + c] = __ldg(tb_tab + (size_t)tidx * CDIM + c);
            }
        }
#pragma unroll
        for (int h = 0; h < 2; h++) {
            uint4 rr[4], tt[4];
#pragma unroll
            for (int i = 0; i < 4; i++) {
                const int r0 = __shfl_sync(0xffffffffu, ridx, h * 4 + i);
                const int t0 = __shfl_sync(0xffffffffu, tidx, h * 4 + i);
                rr[i] = __ldg(RTB + (size_t)r0 * 32 + lane);
                tt[i] = __ldg(TTB + (size_t)t0 * 32 + lane);
            }
#pragma unroll
            for (int i = 0; i < 4; i++)
                *reinterpret_cast<uint2*>(reinterpret_cast<char*>(xg)
                    + (lw * 8 + h * 4 + i) * (XQ * 4) + lane * 8) = mul_cvt8(rr[i], tt[i]);
        }
    }
    BARG(barid);

    int it = 0;
    for (int tile = first; tile < ntiles; tile += step, it++) {
        const int s   = it & 1;
        const int rs  = it % 3;
        const int rsn = (it + 1) % 3;
        uint32_t* xb_cur = xg + s * (64 * XQ);
        char*     xb_nxt = reinterpret_cast<char*>(xg + (s ^ 1) * (64 * XQ));
        const bool have_next = (tile + step < ntiles);

        int nridx = 0, ntidx = 0;
        uint4 rr[4], tt[4];

        // ---- issue next-tile idx + rows 0-3 ----
        if (have_next) {
            const int ei = min((tile + step) * 64 + lw * 8 + li, batch - 1);
            nridx = __ldg(route_idx + ei);
            ntidx = __ldg(time_idx  + ei);
#pragma unroll
            for (int i = 0; i < 4; i++) {
                const int r0 = __shfl_sync(0xffffffffu, nridx, i);
                const int t0 = __shfl_sync(0xffffffffu, ntidx, i);
                rr[i] = __ldg(RTB + (size_t)r0 * 32 + lane);
                tt[i] = __ldg(TTB + (size_t)t0 * 32 + lane);
            }
            if (lane < 8) {
#pragma unroll
                for (int c = 0; c < CDIM; c++) {
                    rv5g[(rsn * 64 + lw * 8 + li) * CDIM + c] = __ldg(ra_tab + (size_t)nridx * CDIM + c);
                    tv5g[(rsn * 64 + lw * 8 + li) * CDIM + c] = __ldg(tb_tab + (size_t)ntidx * CDIM + c);
                }
            }
        }

        float acc[2][4][4];
#pragma unroll
        for (int m = 0; m < 2; m++)
#pragma unroll
            for (int n = 0; n < 4; n++)
#pragma unroll
                for (int q = 0; q < 4; q++) acc[m][n][q] = 0.f;

        uint32_t aAddr[2];
#pragma unroll
        for (int m = 0; m < 2; m++)
            aAddr[m] = sm_u32 + (uint32_t)((xb_cur - smu)
                       + (mq * 32 + m * 16 + a_row) * XQ + a_kq) * 4;

        // ---- MMA kc 0-3 (K 0..127) — hides next-tile LDG latency ----
#pragma unroll
        for (int kc = 0; kc < 4; kc++) {
            const uint32_t kb = kc * 32;
            uint32_t bb[8];
            LDSM_X4(bb[0], bb[1], bb[2], bb[3], bAddr[0] + kb);
            LDSM_X4(bb[4], bb[5], bb[6], bb[7], bAddr[1] + kb);
#pragma unroll
            for (int m = 0; m < 2; m++) {
                uint32_t a[4];
                LDSM_X4(a[0], a[1], a[2], a[3], aAddr[m] + kb);
                mma_fp8(acc[m][0], a, bb[0], bb[1]);
                mma_fp8(acc[m][1], a, bb[2], bb[3]);
                mma_fp8(acc[m][2], a, bb[4], bb[5]);
                mma_fp8(acc[m][3], a, bb[6], bb[7]);
            }
        }

        // ---- commit rows 0-3; issue rows 4-7 ----
        if (have_next) {
#pragma unroll
            for (int i = 0; i < 4; i++)
                *reinterpret_cast<uint2*>(xb_nxt + (lw * 8 + i) * (XQ * 4) + lane * 8)
                    = mul_cvt8(rr[i], tt[i]);
#pragma unroll
            for (int i = 0; i < 4; i++) {
                const int r0 = __shfl_sync(0xffffffffu, nridx, 4 + i);
                const int t0 = __shfl_sync(0xffffffffu, ntidx, 4 + i);
                rr[i] = __ldg(RTB + (size_t)r0 * 32 + lane);
                tt[i] = __ldg(TTB + (size_t)t0 * 32 + lane);
            }
        }

        // ---- MMA kc 4-7 (K 128..255) ----
#pragma unroll
        for (int kc = 4; kc < 8; kc++) {
            const uint32_t kb = kc * 32;
            uint32_t bb[8];
            LDSM_X4(bb[0], bb[1], bb[2], bb[3], bAddr[0] + kb);
            LDSM_X4(bb[4], bb[5], bb[6], bb[7], bAddr[1] + kb);
#pragma unroll
            for (int m = 0; m < 2; m++) {
                uint32_t a[4];
                LDSM_X4(a[0], a[1], a[2], a[3], aAddr[m] + kb);
                mma_fp8(acc[m][0], a, bb[0], bb[1]);
                mma_fp8(acc[m][1], a, bb[2], bb[3]);
                mma_fp8(acc[m][2], a, bb[4], bb[5]);
                mma_fp8(acc[m][3], a, bb[6], bb[7]);
            }
        }

        // ---- commit rows 4-7 ----
        if (have_next) {
#pragma unroll
            for (int i = 0; i < 4; i++)
                *reinterpret_cast<uint2*>(xb_nxt + (lw * 8 + 4 + i) * (XQ * 4) + lane * 8)
                    = mul_cvt8(rr[i], tt[i]);
        }

        // ---- fold relu * (fc_w/8192) -> per-row partials (slot s) ----
        float* oacs = oacg + s * 64;
#pragma unroll
        for (int m = 0; m < 2; m++) {
            float p0 = 0.f, p1 = 0.f;
#pragma unroll
            for (int n = 0; n < 4; n++) {
                const int col = nq * 32 + n * 8 + 2 * t;
                const float f0 = fcs[col], f1 = fcs[col + 1];
                p0 = fmaf(f0, fmaxf(acc[m][n][0], 0.f), p0);
                p0 = fmaf(f1, fmaxf(acc[m][n][1], 0.f), p0);
                p1 = fmaf(f0, fmaxf(acc[m][n][2], 0.f), p1);
                p1 = fmaf(f1, fmaxf(acc[m][n][3], 0.f), p1);
            }
            p0 += __shfl_xor_sync(0xffffffffu, p0, 1);
            p0 += __shfl_xor_sync(0xffffffffu, p0, 2);
            p1 += __shfl_xor_sync(0xffffffffu, p1, 1);
            p1 += __shfl_xor_sync(0xffffffffu, p1, 2);
            if (t == 0) {
                const int row = mq * 32 + m * 16 + (lane >> 2);
                atomicAdd(oacs + row, p0);
                atomicAdd(oacs + row + 8, p1);
            }
        }
        BARG(barid);   // partials + slot^1 x-stores complete

        // ---- epilogue: 4 threads/row; reads rv5 slot rs, oac slot s ----
        {
            const int row = lt >> 2;
            const int p   = lt & 3;
            const int eo  = tile * 64 + row;
            const float* rv = rv5g + (rs * 64 + row) * CDIM;
            const float* tv = tv5g + (rs * 64 + row) * CDIM;
            const int start = p ? (1 + p * 6) : 0;
            const int cnt   = p ? 6 : 7;
            float val = 0.f;
#pragma unroll
            for (int k = 0; k < 7; k++) {
                if (k < cnt) {
                    const int idx = start + k;
                    const int i5  = idx / 5, j5 = idx - 5 * i5;
                    const float x  = fmaf(rv[i5], tv[j5], bia[idx]);
                    const float sg = 1.0f / (1.0f + __expf(-x));
                    val = fmaf(fci[idx], sg, val);
                }
            }
            val += __shfl_xor_sync(0xffffffffu, val, 1);
            val += __shfl_xor_sync(0xffffffffu, val, 2);
            if (p == 0) {
                if (eo < batch) out[eo] = fcb + oacs[row] + val;
                oacs[row] = 0.f;
            }
        }
        // next tile uses oac slot s^1, rv5 slot rsn; slot-s reuse fenced by next BARG
    }
}

// ---------------------------------------------------------------------------
extern "C" void kernel_launch(void* const* d_in, const int* in_sizes, int n_in,
                              void* d_out, int out_size)
{
    const int*   route_idx   = (const int*)  d_in[0];
    const int*   time_idx    = (const int*)  d_in[1];
    const float* route_table = (const float*)d_in[2];
    const float* time_table  = (const float*)d_in[3];
    const float* w           = (const float*)d_in[4];
    const float* mode_a      = (const float*)d_in[5];
    const float* mode_b      = (const float*)d_in[6];
    const float* mode_bias   = (const float*)d_in[7];
    const float* fc_w        = (const float*)d_in[8];
    const float* fc_b        = (const float*)d_in[9];
    float*       out         = (float*)d_out;

    const int batch    = in_sizes[0];
    const int n_routes = in_sizes[2] / DIM;
    const int n_time   = in_sizes[3] / DIM;

    float *ra_ptr = nullptr, *tb_ptr = nullptr;
    __half *rtb_ptr = nullptr, *ttb_ptr = nullptr;
    cudaGetSymbolAddress((void**)&ra_ptr,  g_ra);
    cudaGetSymbolAddress((void**)&tb_ptr,  g_tb);
    cudaGetSymbolAddress((void**)&rtb_ptr, g_rtb);
    cudaGetSymbolAddress((void**)&ttb_ptr, g_ttb);

    {
        const int total = n_routes + n_time;
        proj_conv<<<(total + 63) / 64, 512>>>(route_table, time_table, mode_a, mode_b,
                                              ra_ptr, tb_ptr, rtb_ptr, ttb_ptr,
                                              n_routes, n_time);
    }

    const int ntiles = (batch + 63) / 64;
    const int smem_bytes = SM_WORDS * 4;   // 121600
    cudaFuncSetAttribute(main_kernel, cudaFuncAttributeMaxDynamicSharedMemorySize, smem_bytes);

    int grid = 148;
    main_kernel<<<grid, 512, smem_bytes>>>(route_idx, time_idx,
                                           (const uint4*)rtb_ptr, (const uint4*)ttb_ptr,
                                           w, fc_w, fc_b, mode_bias,
                                           ra_ptr, tb_ptr, out, batch, ntiles);
}